// round 2
// baseline (speedup 1.0000x reference)
#include <cuda_runtime.h>
#include <cstdint>

#define NTOK  64
#define HID   2048
#define INTER 1408
#define NEXP  32
#define TOPK  4
#define NASS  (NTOK*TOPK)

typedef unsigned long long ull;

// ---------------- scratch (no allocation allowed) ----------------
__device__ int   g_cnt[NEXP];
__device__ int   g_off[NEXP];
__device__ int   g_tok[NASS];          // token id per assignment (bucketed by expert)
__device__ float g_wass[NASS];         // routing weight per assignment
__device__ int   g_aidx[NASS];         // [t][j] -> assignment slot
__device__ float g_mixed[(size_t)NASS*INTER];  // silu(gate)*up per assignment
__device__ float g_part [(size_t)NASS*HID];    // weighted down-proj per assignment

// ---------------- f32x2 packed FMA (sm_100+) ----------------
__device__ __forceinline__ void fma2(ull &a, ull b, ull c) {
    asm("fma.rn.f32x2 %0, %1, %2, %0;" : "+l"(a) : "l"(b), "l"(c));
}
__device__ __forceinline__ float hsum(ull a) {
    float lo = __uint_as_float((unsigned)a);
    float hi = __uint_as_float((unsigned)(a >> 32));
    float s = lo + hi;
    #pragma unroll
    for (int o = 16; o > 0; o >>= 1) s += __shfl_xor_sync(0xffffffffu, s, o);
    return s;
}

// ---------------- 1) routing: top-4 + softmax + deterministic buckets ----------------
__global__ void route_k(const float* __restrict__ logits) {
    __shared__ int   s_ids[NTOK][TOPK];
    __shared__ float s_w  [NTOK][TOPK];
    __shared__ int   s_cnt[NEXP];
    __shared__ int   s_off[NEXP];
    int t = threadIdx.x;  // 64 threads

    float v[NEXP];
    #pragma unroll
    for (int e = 0; e < NEXP; e++) v[e] = logits[t*NEXP + e];

    int ids[TOPK]; float vals[TOPK];
    #pragma unroll
    for (int j = 0; j < TOPK; j++) {
        int bi = 0; float bv = -1e30f;
        #pragma unroll
        for (int e = 0; e < NEXP; e++) if (v[e] > bv) { bv = v[e]; bi = e; }
        ids[j] = bi; vals[j] = bv; v[bi] = -1e30f;
    }
    float m = vals[0], s = 0.f, w[TOPK];
    #pragma unroll
    for (int j = 0; j < TOPK; j++) { w[j] = __expf(vals[j] - m); s += w[j]; }
    float inv = 1.f / s;
    #pragma unroll
    for (int j = 0; j < TOPK; j++) { w[j] *= inv; s_ids[t][j] = ids[j]; s_w[t][j] = w[j]; }
    __syncthreads();

    if (t < NEXP) {
        int c = 0;
        for (int tt = 0; tt < NTOK; tt++)
            #pragma unroll
            for (int jj = 0; jj < TOPK; jj++) if (s_ids[tt][jj] == t) c++;
        s_cnt[t] = c;
    }
    __syncthreads();
    if (t < NEXP) {
        int o = 0;
        for (int e = 0; e < t; e++) o += s_cnt[e];
        s_off[t] = o; g_cnt[t] = s_cnt[t]; g_off[t] = o;
    }
    __syncthreads();

    // deterministic rank: number of earlier tokens choosing the same expert
    #pragma unroll
    for (int j = 0; j < TOPK; j++) {
        int e = s_ids[t][j];
        int r = 0;
        for (int tt = 0; tt < t; tt++)
            #pragma unroll
            for (int jj = 0; jj < TOPK; jj++) if (s_ids[tt][jj] == e) r++;
        int slot = s_off[e] + r;
        g_tok[slot]  = t;
        g_wass[slot] = s_w[t][j];
        g_aidx[t*TOPK + j] = slot;
    }
}

// ---------------- 2) gate/up GEMM: M=cnt, N=1408, K=2048 ----------------
// block = (row_tile 128, expert). 8 warps; warp owns 8 row-pairs (TN=2).
// Weight streams are register double-buffered (prefetch distance PF) so the
// LDG.128s for window i+PF are in flight while the FMAs for window i execute.
#define GU_ROWS_BLK 128
#define GU_TILES    (INTER / GU_ROWS_BLK)   // 11

template<int TM, int PF>
__device__ __forceinline__ void gu_rows(const float* __restrict__ wg_e,
                                        const float* __restrict__ wu_e,
                                        const ulonglong2* __restrict__ xs,
                                        int row0, int slot0, int rem)
{
    const int warp = threadIdx.x >> 5, lane = threadIdx.x & 31;
    for (int rp = 0; rp < 8; rp++) {
        int row = row0 + warp * 16 + rp * 2;
        const ulonglong2* g0 = reinterpret_cast<const ulonglong2*>(wg_e + (size_t)row    * HID);
        const ulonglong2* g1 = reinterpret_cast<const ulonglong2*>(wg_e + (size_t)(row+1)* HID);
        const ulonglong2* u0 = reinterpret_cast<const ulonglong2*>(wu_e + (size_t)row    * HID);
        const ulonglong2* u1 = reinterpret_cast<const ulonglong2*>(wu_e + (size_t)(row+1)* HID);
        ull ag0[TM], ag1[TM], au0[TM], au1[TM];
        #pragma unroll
        for (int t = 0; t < TM; t++) { ag0[t]=0ull; ag1[t]=0ull; au0[t]=0ull; au1[t]=0ull; }

        // pipeline prologue
        ulonglong2 p0, p1, p2, p3;          // window i (PF==1) / i (PF==2 front)
        ulonglong2 q0, q1, q2, q3;          // window i+1 (PF==2 only)
        p0 = g0[lane]; p1 = g1[lane]; p2 = u0[lane]; p3 = u1[lane];
        if (PF == 2) {
            int o = lane + 32;
            q0 = g0[o]; q1 = g1[o]; q2 = u0[o]; q3 = u1[o];
        }

        #pragma unroll
        for (int i = 0; i < 16; i++) {
            ulonglong2 c0 = p0, c1 = p1, c2 = p2, c3 = p3;
            if (PF == 2) {
                p0 = q0; p1 = q1; p2 = q2; p3 = q3;
                if (i + 2 < 16) {
                    int o = lane + ((i + 2) << 5);
                    q0 = g0[o]; q1 = g1[o]; q2 = u0[o]; q3 = u1[o];
                }
            } else {
                if (i + 1 < 16) {
                    int o = lane + ((i + 1) << 5);
                    p0 = g0[o]; p1 = g1[o]; p2 = u0[o]; p3 = u1[o];
                }
            }
            int o = lane + (i << 5);
            #pragma unroll
            for (int t = 0; t < TM; t++) {
                ulonglong2 xv = xs[t * 512 + o];
                fma2(ag0[t], c0.x, xv.x); fma2(ag0[t], c0.y, xv.y);
                fma2(ag1[t], c1.x, xv.x); fma2(ag1[t], c1.y, xv.y);
                fma2(au0[t], c2.x, xv.x); fma2(au0[t], c2.y, xv.y);
                fma2(au1[t], c3.x, xv.x); fma2(au1[t], c3.y, xv.y);
            }
        }
        #pragma unroll
        for (int t = 0; t < TM; t++) {
            float gA = hsum(ag0[t]);
            float gB = hsum(ag1[t]);
            float uA = hsum(au0[t]);
            float uB = hsum(au1[t]);
            if (lane == t && t < rem) {
                float sA = gA * __frcp_rn(1.f + __expf(-gA));
                float sB = gB * __frcp_rn(1.f + __expf(-gB));
                float* mp = g_mixed + (size_t)(slot0 + t) * INTER;
                mp[row]     = sA * uA;
                mp[row + 1] = sB * uB;
            }
        }
    }
}

__global__ void __launch_bounds__(256, 1) gateup_k(const float* __restrict__ x,
                                                   const float* __restrict__ wg,
                                                   const float* __restrict__ wu)
{
    extern __shared__ ulonglong2 sh[];
    int e = blockIdx.y;
    int cnt = g_cnt[e];
    if (cnt == 0) return;
    int base = g_off[e];
    int row0 = blockIdx.x * GU_ROWS_BLK;
    const float* wg_e = wg + (size_t)e * INTER * HID;
    const float* wu_e = wu + (size_t)e * INTER * HID;

    for (int s0 = 0; s0 < cnt; s0 += 16) {
        int rem = cnt - s0; if (rem > 16) rem = 16;
        int tmv = rem <= 4 ? 4 : rem <= 8 ? 8 : rem <= 12 ? 12 : 16;
        __syncthreads();
        for (int idx = threadIdx.x; idx < tmv * 512; idx += 256) {
            int slot = idx >> 9, j = idx & 511;
            ulonglong2 v;
            if (slot < rem) {
                int tok = g_tok[base + s0 + slot];
                v = reinterpret_cast<const ulonglong2*>(x + (size_t)tok * HID)[j];
            } else { v.x = 0ull; v.y = 0ull; }
            sh[idx] = v;
        }
        __syncthreads();
        if      (tmv == 4 ) gu_rows<4 , 2>(wg_e, wu_e, sh, row0, base + s0, rem);
        else if (tmv == 8 ) gu_rows<8 , 2>(wg_e, wu_e, sh, row0, base + s0, rem);
        else if (tmv == 12) gu_rows<12, 2>(wg_e, wu_e, sh, row0, base + s0, rem);
        else                gu_rows<16, 1>(wg_e, wu_e, sh, row0, base + s0, rem);
    }
}

// ---------------- 3) down GEMM: M=cnt, N=2048, K=1408 ----------------
// block = (row_tile 128, expert). warp owns 4 row-quads (TN=4). Same
// register double-buffered pipeline on the 4 weight streams.
#define DN_ROWS_BLK 128
#define DN_TILES    (HID / DN_ROWS_BLK)   // 16

template<int TM, int PF>
__device__ __forceinline__ void dn_rows(const float* __restrict__ wd_e,
                                        const ulonglong2* __restrict__ xs,
                                        int row0, int slot0, int rem)
{
    const int warp = threadIdx.x >> 5, lane = threadIdx.x & 31;
    for (int q = 0; q < 4; q++) {
        int row = row0 + warp * 16 + q * 4;
        const ulonglong2* d0 = reinterpret_cast<const ulonglong2*>(wd_e + (size_t)(row  ) * INTER);
        const ulonglong2* d1 = reinterpret_cast<const ulonglong2*>(wd_e + (size_t)(row+1) * INTER);
        const ulonglong2* d2 = reinterpret_cast<const ulonglong2*>(wd_e + (size_t)(row+2) * INTER);
        const ulonglong2* d3 = reinterpret_cast<const ulonglong2*>(wd_e + (size_t)(row+3) * INTER);
        ull a0[TM], a1[TM], a2[TM], a3[TM];
        #pragma unroll
        for (int t = 0; t < TM; t++) { a0[t]=0ull; a1[t]=0ull; a2[t]=0ull; a3[t]=0ull; }

        ulonglong2 p0, p1, p2, p3;
        ulonglong2 q0v, q1v, q2v, q3v;
        p0 = d0[lane]; p1 = d1[lane]; p2 = d2[lane]; p3 = d3[lane];
        if (PF == 2) {
            int o = lane + 32;
            q0v = d0[o]; q1v = d1[o]; q2v = d2[o]; q3v = d3[o];
        }

        #pragma unroll
        for (int i = 0; i < 11; i++) {   // 1408/4 = 352 = 32*11
            ulonglong2 c0 = p0, c1 = p1, c2 = p2, c3 = p3;
            if (PF == 2) {
                p0 = q0v; p1 = q1v; p2 = q2v; p3 = q3v;
                if (i + 2 < 11) {
                    int o = lane + ((i + 2) << 5);
                    q0v = d0[o]; q1v = d1[o]; q2v = d2[o]; q3v = d3[o];
                }
            } else {
                if (i + 1 < 11) {
                    int o = lane + ((i + 1) << 5);
                    p0 = d0[o]; p1 = d1[o]; p2 = d2[o]; p3 = d3[o];
                }
            }
            int o = lane + (i << 5);
            #pragma unroll
            for (int t = 0; t < TM; t++) {
                ulonglong2 xv = xs[t * 352 + o];
                fma2(a0[t], c0.x, xv.x); fma2(a0[t], c0.y, xv.y);
                fma2(a1[t], c1.x, xv.x); fma2(a1[t], c1.y, xv.y);
                fma2(a2[t], c2.x, xv.x); fma2(a2[t], c2.y, xv.y);
                fma2(a3[t], c3.x, xv.x); fma2(a3[t], c3.y, xv.y);
            }
        }
        #pragma unroll
        for (int t = 0; t < TM; t++) {
            float s0v = hsum(a0[t]);
            float s1v = hsum(a1[t]);
            float s2v = hsum(a2[t]);
            float s3v = hsum(a3[t]);
            if (lane == t && t < rem) {
                float w = g_wass[slot0 + t];
                float* pp = g_part + (size_t)(slot0 + t) * HID;
                pp[row]     = s0v * w;
                pp[row + 1] = s1v * w;
                pp[row + 2] = s2v * w;
                pp[row + 3] = s3v * w;
            }
        }
    }
}

__global__ void __launch_bounds__(256, 1) down_k(const float* __restrict__ wd)
{
    extern __shared__ ulonglong2 sh[];
    int e = blockIdx.y;
    int cnt = g_cnt[e];
    if (cnt == 0) return;
    int base = g_off[e];
    int row0 = blockIdx.x * DN_ROWS_BLK;
    const float* wd_e = wd + (size_t)e * HID * INTER;

    for (int s0 = 0; s0 < cnt; s0 += 16) {
        int rem = cnt - s0; if (rem > 16) rem = 16;
        int tmv = rem <= 4 ? 4 : rem <= 8 ? 8 : rem <= 12 ? 12 : 16;
        __syncthreads();
        for (int idx = threadIdx.x; idx < tmv * 352; idx += 256) {
            int slot = idx / 352, j = idx - slot * 352;
            ulonglong2 v;
            if (slot < rem) {
                v = reinterpret_cast<const ulonglong2*>(g_mixed + (size_t)(base + s0 + slot) * INTER)[j];
            } else { v.x = 0ull; v.y = 0ull; }
            sh[idx] = v;
        }
        __syncthreads();
        if      (tmv == 4 ) dn_rows<4 , 2>(wd_e, sh, row0, base + s0, rem);
        else if (tmv == 8 ) dn_rows<8 , 2>(wd_e, sh, row0, base + s0, rem);
        else if (tmv == 12) dn_rows<12, 2>(wd_e, sh, row0, base + s0, rem);
        else                dn_rows<16, 1>(wd_e, sh, row0, base + s0, rem);
    }
}

// ---------------- 4) gather: out[t,h] = sum_j part[aidx[t][j]][h] ----------------
__global__ void gather_k(float* __restrict__ out)
{
    int idx = blockIdx.x * 256 + threadIdx.x;     // 131072 total
    int t = idx >> 11;
    int h = idx & 2047;
    const int* ai = g_aidx + t * TOPK;
    float s = 0.f;
    #pragma unroll
    for (int j = 0; j < TOPK; j++) s += g_part[(size_t)ai[j] * HID + h];
    out[idx] = s;
}

// ---------------- launch ----------------
extern "C" void kernel_launch(void* const* d_in, const int* in_sizes, int n_in,
                              void* d_out, int out_size)
{
    const float* x      = (const float*)d_in[0];
    const float* logits = (const float*)d_in[1];
    const float* wg     = (const float*)d_in[2];
    const float* wu     = (const float*)d_in[3];
    const float* wd     = (const float*)d_in[4];
    float* out = (float*)d_out;

    const int GU_SMEM = 16 * 512 * (int)sizeof(ulonglong2);   // 131072
    const int DN_SMEM = 16 * 352 * (int)sizeof(ulonglong2);   // 90112
    cudaFuncSetAttribute(gateup_k, cudaFuncAttributeMaxDynamicSharedMemorySize, GU_SMEM);
    cudaFuncSetAttribute(down_k,   cudaFuncAttributeMaxDynamicSharedMemorySize, DN_SMEM);

    route_k<<<1, NTOK>>>(logits);
    gateup_k<<<dim3(GU_TILES, NEXP), 256, GU_SMEM>>>(x, wg, wu);
    down_k  <<<dim3(DN_TILES, NEXP), 256, DN_SMEM>>>(wd);
    gather_k<<<(NTOK * HID) / 256, 256>>>(out);
}

// round 3
// speedup vs baseline: 1.9144x; 1.9144x over previous
#include <cuda_runtime.h>
#include <cstdint>

#define NTOK  64
#define HID   2048
#define INTER 1408
#define NEXP  32
#define TOPK  4
#define NASS  (NTOK*TOPK)

typedef unsigned long long ull;

// ---------------- scratch (no allocation allowed) ----------------
__device__ int   g_cnt[NEXP];
__device__ int   g_off[NEXP];
__device__ int   g_tok[NASS];          // token id per assignment (bucketed by expert)
__device__ float g_wass[NASS];         // routing weight per assignment
__device__ int   g_aidx[NASS];         // [t][j] -> assignment slot
__device__ float g_mixed[(size_t)NASS*INTER];  // silu(gate)*up per assignment
__device__ float g_part [(size_t)NASS*HID];    // weighted down-proj per assignment

// ---------------- f32x2 packed FMA (sm_100+) ----------------
__device__ __forceinline__ void fma2(ull &a, ull b, ull c) {
    asm("fma.rn.f32x2 %0, %1, %2, %0;" : "+l"(a) : "l"(b), "l"(c));
}
__device__ __forceinline__ float hsum(ull a) {
    float lo = __uint_as_float((unsigned)a);
    float hi = __uint_as_float((unsigned)(a >> 32));
    float s = lo + hi;
    #pragma unroll
    for (int o = 16; o > 0; o >>= 1) s += __shfl_xor_sync(0xffffffffu, s, o);
    return s;
}

// ---------------- 1) routing: top-4 + softmax + deterministic buckets ----------------
__global__ void route_k(const float* __restrict__ logits) {
    __shared__ int   s_ids[NTOK][TOPK];
    __shared__ float s_w  [NTOK][TOPK];
    __shared__ int   s_cnt[NEXP];
    __shared__ int   s_off[NEXP];
    int t = threadIdx.x;  // 64 threads

    float v[NEXP];
    #pragma unroll
    for (int e = 0; e < NEXP; e++) v[e] = logits[t*NEXP + e];

    int ids[TOPK]; float vals[TOPK];
    #pragma unroll
    for (int j = 0; j < TOPK; j++) {
        int bi = 0; float bv = -1e30f;
        #pragma unroll
        for (int e = 0; e < NEXP; e++) if (v[e] > bv) { bv = v[e]; bi = e; }
        ids[j] = bi; vals[j] = bv; v[bi] = -1e30f;
    }
    float m = vals[0], s = 0.f, w[TOPK];
    #pragma unroll
    for (int j = 0; j < TOPK; j++) { w[j] = __expf(vals[j] - m); s += w[j]; }
    float inv = 1.f / s;
    #pragma unroll
    for (int j = 0; j < TOPK; j++) { w[j] *= inv; s_ids[t][j] = ids[j]; s_w[t][j] = w[j]; }
    __syncthreads();

    if (t < NEXP) {
        int c = 0;
        for (int tt = 0; tt < NTOK; tt++)
            #pragma unroll
            for (int jj = 0; jj < TOPK; jj++) if (s_ids[tt][jj] == t) c++;
        s_cnt[t] = c;
    }
    __syncthreads();
    if (t < NEXP) {
        int o = 0;
        for (int e = 0; e < t; e++) o += s_cnt[e];
        s_off[t] = o; g_cnt[t] = s_cnt[t]; g_off[t] = o;
    }
    __syncthreads();

    // deterministic rank: number of earlier tokens choosing the same expert
    #pragma unroll
    for (int j = 0; j < TOPK; j++) {
        int e = s_ids[t][j];
        int r = 0;
        for (int tt = 0; tt < t; tt++)
            #pragma unroll
            for (int jj = 0; jj < TOPK; jj++) if (s_ids[tt][jj] == e) r++;
        int slot = s_off[e] + r;
        g_tok[slot]  = t;
        g_wass[slot] = s_w[t][j];
        g_aidx[t*TOPK + j] = slot;
    }
}

// ---------------- 2) gate/up GEMM: M=cnt, N=1408, K=2048 ----------------
// block = (row_tile 128, chunk, expert). 8 warps; warp owns 8 row-pairs (TN=2).
// x tile (<=8 tokens, 64 KB) in smem -> 2 blocks/SM. Chunk 0 handles slots
// [0,8); chunk 1 loops slots [8,16),[16,24)... so both chunks of an expert run
// concurrently and the second one's weight reads hit L2.
#define GU_ROWS_BLK 128
#define GU_TILES    (INTER / GU_ROWS_BLK)   // 11
#define TMCAP 8

template<int TM>
__device__ __forceinline__ void gu_rows(const float* __restrict__ wg_e,
                                        const float* __restrict__ wu_e,
                                        const ulonglong2* __restrict__ xs,
                                        int row0, int slot0, int rem)
{
    const int warp = threadIdx.x >> 5, lane = threadIdx.x & 31;
    for (int rp = 0; rp < 8; rp++) {
        int row = row0 + warp * 16 + rp * 2;
        const ulonglong2* g0 = reinterpret_cast<const ulonglong2*>(wg_e + (size_t)row    * HID);
        const ulonglong2* g1 = reinterpret_cast<const ulonglong2*>(wg_e + (size_t)(row+1)* HID);
        const ulonglong2* u0 = reinterpret_cast<const ulonglong2*>(wu_e + (size_t)row    * HID);
        const ulonglong2* u1 = reinterpret_cast<const ulonglong2*>(wu_e + (size_t)(row+1)* HID);
        ull ag0[TM], ag1[TM], au0[TM], au1[TM];
        #pragma unroll
        for (int t = 0; t < TM; t++) { ag0[t]=0ull; ag1[t]=0ull; au0[t]=0ull; au1[t]=0ull; }
        #pragma unroll 4
        for (int i = 0; i < 16; i++) {
            int o = lane + (i << 5);
            ulonglong2 a0 = g0[o], a1 = g1[o], b0 = u0[o], b1 = u1[o];
            #pragma unroll
            for (int t = 0; t < TM; t++) {
                ulonglong2 xv = xs[t * 512 + o];
                fma2(ag0[t], a0.x, xv.x); fma2(ag0[t], a0.y, xv.y);
                fma2(ag1[t], a1.x, xv.x); fma2(ag1[t], a1.y, xv.y);
                fma2(au0[t], b0.x, xv.x); fma2(au0[t], b0.y, xv.y);
                fma2(au1[t], b1.x, xv.x); fma2(au1[t], b1.y, xv.y);
            }
        }
        #pragma unroll
        for (int t = 0; t < TM; t++) {
            float gA = hsum(ag0[t]);
            float gB = hsum(ag1[t]);
            float uA = hsum(au0[t]);
            float uB = hsum(au1[t]);
            if (lane == t && t < rem) {
                float sA = gA * __frcp_rn(1.f + __expf(-gA));
                float sB = gB * __frcp_rn(1.f + __expf(-gB));
                float* mp = g_mixed + (size_t)(slot0 + t) * INTER;
                mp[row]     = sA * uA;
                mp[row + 1] = sB * uB;
            }
        }
    }
}

__global__ void __launch_bounds__(256, 2) gateup_k(const float* __restrict__ x,
                                                   const float* __restrict__ wg,
                                                   const float* __restrict__ wu)
{
    extern __shared__ ulonglong2 sh[];
    int e = blockIdx.z;
    int cnt = g_cnt[e];
    int chunk = blockIdx.y;
    if (cnt == 0) return;
    if (chunk == 1 && cnt <= TMCAP) return;
    int base = g_off[e];
    int row0 = blockIdx.x * GU_ROWS_BLK;
    const float* wg_e = wg + (size_t)e * INTER * HID;
    const float* wu_e = wu + (size_t)e * INTER * HID;

    int s_begin = (chunk == 0) ? 0 : TMCAP;
    int s_end   = (chunk == 0) ? TMCAP : cnt;

    for (int s0 = s_begin; s0 < s_end && s0 < cnt; s0 += TMCAP) {
        int rem = cnt - s0; if (rem > TMCAP) rem = TMCAP;
        int tmv = rem <= 4 ? 4 : 8;
        __syncthreads();
        for (int idx = threadIdx.x; idx < tmv * 512; idx += 256) {
            int slot = idx >> 9, j = idx & 511;
            ulonglong2 v;
            if (slot < rem) {
                int tok = g_tok[base + s0 + slot];
                v = reinterpret_cast<const ulonglong2*>(x + (size_t)tok * HID)[j];
            } else { v.x = 0ull; v.y = 0ull; }
            sh[idx] = v;
        }
        __syncthreads();
        if (tmv == 4) gu_rows<4>(wg_e, wu_e, sh, row0, base + s0, rem);
        else          gu_rows<8>(wg_e, wu_e, sh, row0, base + s0, rem);
    }
}

// ---------------- 3) down GEMM: M=cnt, N=2048, K=1408 ----------------
// block = (row_tile 128, chunk, expert). warp owns 4 row-quads (TN=4).
#define DN_ROWS_BLK 128
#define DN_TILES    (HID / DN_ROWS_BLK)   // 16

template<int TM>
__device__ __forceinline__ void dn_rows(const float* __restrict__ wd_e,
                                        const ulonglong2* __restrict__ xs,
                                        int row0, int slot0, int rem)
{
    const int warp = threadIdx.x >> 5, lane = threadIdx.x & 31;
    for (int q = 0; q < 4; q++) {
        int row = row0 + warp * 16 + q * 4;
        const ulonglong2* d0 = reinterpret_cast<const ulonglong2*>(wd_e + (size_t)(row  ) * INTER);
        const ulonglong2* d1 = reinterpret_cast<const ulonglong2*>(wd_e + (size_t)(row+1) * INTER);
        const ulonglong2* d2 = reinterpret_cast<const ulonglong2*>(wd_e + (size_t)(row+2) * INTER);
        const ulonglong2* d3 = reinterpret_cast<const ulonglong2*>(wd_e + (size_t)(row+3) * INTER);
        ull a0[TM], a1[TM], a2[TM], a3[TM];
        #pragma unroll
        for (int t = 0; t < TM; t++) { a0[t]=0ull; a1[t]=0ull; a2[t]=0ull; a3[t]=0ull; }
        #pragma unroll
        for (int i = 0; i < 11; i++) {   // 1408/4 = 352 = 32*11
            int o = lane + (i << 5);
            ulonglong2 w0 = d0[o], w1 = d1[o], w2 = d2[o], w3 = d3[o];
            #pragma unroll
            for (int t = 0; t < TM; t++) {
                ulonglong2 xv = xs[t * 352 + o];
                fma2(a0[t], w0.x, xv.x); fma2(a0[t], w0.y, xv.y);
                fma2(a1[t], w1.x, xv.x); fma2(a1[t], w1.y, xv.y);
                fma2(a2[t], w2.x, xv.x); fma2(a2[t], w2.y, xv.y);
                fma2(a3[t], w3.x, xv.x); fma2(a3[t], w3.y, xv.y);
            }
        }
        #pragma unroll
        for (int t = 0; t < TM; t++) {
            float s0v = hsum(a0[t]);
            float s1v = hsum(a1[t]);
            float s2v = hsum(a2[t]);
            float s3v = hsum(a3[t]);
            if (lane == t && t < rem) {
                float w = g_wass[slot0 + t];
                float* pp = g_part + (size_t)(slot0 + t) * HID;
                pp[row]     = s0v * w;
                pp[row + 1] = s1v * w;
                pp[row + 2] = s2v * w;
                pp[row + 3] = s3v * w;
            }
        }
    }
}

__global__ void __launch_bounds__(256, 2) down_k(const float* __restrict__ wd)
{
    extern __shared__ ulonglong2 sh[];
    int e = blockIdx.z;
    int cnt = g_cnt[e];
    int chunk = blockIdx.y;
    if (cnt == 0) return;
    if (chunk == 1 && cnt <= TMCAP) return;
    int base = g_off[e];
    int row0 = blockIdx.x * DN_ROWS_BLK;
    const float* wd_e = wd + (size_t)e * HID * INTER;

    int s_begin = (chunk == 0) ? 0 : TMCAP;
    int s_end   = (chunk == 0) ? TMCAP : cnt;

    for (int s0 = s_begin; s0 < s_end && s0 < cnt; s0 += TMCAP) {
        int rem = cnt - s0; if (rem > TMCAP) rem = TMCAP;
        int tmv = rem <= 4 ? 4 : 8;
        __syncthreads();
        for (int idx = threadIdx.x; idx < tmv * 352; idx += 256) {
            int slot = idx / 352, j = idx - slot * 352;
            ulonglong2 v;
            if (slot < rem) {
                v = reinterpret_cast<const ulonglong2*>(g_mixed + (size_t)(base + s0 + slot) * INTER)[j];
            } else { v.x = 0ull; v.y = 0ull; }
            sh[idx] = v;
        }
        __syncthreads();
        if (tmv == 4) dn_rows<4>(wd_e, sh, row0, base + s0, rem);
        else          dn_rows<8>(wd_e, sh, row0, base + s0, rem);
    }
}

// ---------------- 4) gather: out[t,h] = sum_j part[aidx[t][j]][h] ----------------
__global__ void gather_k(float* __restrict__ out)
{
    int idx = blockIdx.x * 256 + threadIdx.x;     // 131072 total
    int t = idx >> 11;
    int h = idx & 2047;
    const int* ai = g_aidx + t * TOPK;
    float s = 0.f;
    #pragma unroll
    for (int j = 0; j < TOPK; j++) s += g_part[(size_t)ai[j] * HID + h];
    out[idx] = s;
}

// ---------------- launch ----------------
extern "C" void kernel_launch(void* const* d_in, const int* in_sizes, int n_in,
                              void* d_out, int out_size)
{
    const float* x      = (const float*)d_in[0];
    const float* logits = (const float*)d_in[1];
    const float* wg     = (const float*)d_in[2];
    const float* wu     = (const float*)d_in[3];
    const float* wd     = (const float*)d_in[4];
    float* out = (float*)d_out;

    const int GU_SMEM = TMCAP * 512 * (int)sizeof(ulonglong2);   // 65536
    const int DN_SMEM = TMCAP * 352 * (int)sizeof(ulonglong2);   // 45056
    cudaFuncSetAttribute(gateup_k, cudaFuncAttributeMaxDynamicSharedMemorySize, GU_SMEM);
    cudaFuncSetAttribute(down_k,   cudaFuncAttributeMaxDynamicSharedMemorySize, DN_SMEM);

    route_k<<<1, NTOK>>>(logits);
    gateup_k<<<dim3(GU_TILES, 2, NEXP), 256, GU_SMEM>>>(x, wg, wu);
    down_k  <<<dim3(DN_TILES, 2, NEXP), 256, DN_SMEM>>>(wd);
    gather_k<<<(NTOK * HID) / 256, 256>>>(out);
}

// round 4
// speedup vs baseline: 4.0109x; 2.0951x over previous
#include <cuda_runtime.h>
#include <cstdint>

#define NTOK  64
#define HID   2048
#define INTER 1408
#define NEXP  32
#define TOPK  4
#define NASS  (NTOK*TOPK)

typedef unsigned long long ull;

// ---------------- scratch (no allocation allowed) ----------------
__device__ int   g_cnt[NEXP];
__device__ int   g_off[NEXP];
__device__ int   g_tok[NASS];
__device__ float g_wass[NASS];
__device__ int   g_aidx[NASS];
__device__ float g_mixed[(size_t)NASS*INTER];
__device__ float g_part [(size_t)NASS*HID];

// ---------------- f32x2 packed FMA ----------------
__device__ __forceinline__ void fma2(ull &a, ull b, ull c) {
    asm("fma.rn.f32x2 %0, %1, %2, %0;" : "+l"(a) : "l"(b), "l"(c));
}
__device__ __forceinline__ float hsum(ull a) {
    float lo = __uint_as_float((unsigned)a);
    float hi = __uint_as_float((unsigned)(a >> 32));
    float s = lo + hi;
    #pragma unroll
    for (int o = 16; o > 0; o >>= 1) s += __shfl_xor_sync(0xffffffffu, s, o);
    return s;
}

// ---------------- cp.async helpers ----------------
__device__ __forceinline__ void cpa16(uint32_t dst, const float* src) {
    asm volatile("cp.async.cg.shared.global [%0], [%1], 16;" :: "r"(dst), "l"(src));
}
__device__ __forceinline__ void cpa_commit() { asm volatile("cp.async.commit_group;"); }
__device__ __forceinline__ void cpa_wait1()  { asm volatile("cp.async.wait_group 1;"); }

// ---------------- 1) routing ----------------
__global__ void route_k(const float* __restrict__ logits) {
    __shared__ int   s_ids[NTOK][TOPK];
    __shared__ float s_w  [NTOK][TOPK];
    __shared__ int   s_cnt[NEXP];
    __shared__ int   s_off[NEXP];
    int t = threadIdx.x;

    float v[NEXP];
    #pragma unroll
    for (int e = 0; e < NEXP; e++) v[e] = logits[t*NEXP + e];

    int ids[TOPK]; float vals[TOPK];
    #pragma unroll
    for (int j = 0; j < TOPK; j++) {
        int bi = 0; float bv = -1e30f;
        #pragma unroll
        for (int e = 0; e < NEXP; e++) if (v[e] > bv) { bv = v[e]; bi = e; }
        ids[j] = bi; vals[j] = bv; v[bi] = -1e30f;
    }
    float m = vals[0], s = 0.f, w[TOPK];
    #pragma unroll
    for (int j = 0; j < TOPK; j++) { w[j] = __expf(vals[j] - m); s += w[j]; }
    float inv = 1.f / s;
    #pragma unroll
    for (int j = 0; j < TOPK; j++) { w[j] *= inv; s_ids[t][j] = ids[j]; s_w[t][j] = w[j]; }
    __syncthreads();

    if (t < NEXP) {
        int c = 0;
        for (int tt = 0; tt < NTOK; tt++)
            #pragma unroll
            for (int jj = 0; jj < TOPK; jj++) if (s_ids[tt][jj] == t) c++;
        s_cnt[t] = c;
    }
    __syncthreads();
    if (t < NEXP) {
        int o = 0;
        for (int e = 0; e < t; e++) o += s_cnt[e];
        s_off[t] = o; g_cnt[t] = s_cnt[t]; g_off[t] = o;
    }
    __syncthreads();

    #pragma unroll
    for (int j = 0; j < TOPK; j++) {
        int e = s_ids[t][j];
        int r = 0;
        for (int tt = 0; tt < t; tt++)
            #pragma unroll
            for (int jj = 0; jj < TOPK; jj++) if (s_ids[tt][jj] == e) r++;
        int slot = s_off[e] + r;
        g_tok[slot]  = t;
        g_wass[slot] = s_w[t][j];
        g_aidx[t*TOPK + j] = slot;
    }
}

// ================= 2) gate/up GEMM: M=cnt, N=1408, K=2048 =================
// block = (row_tile 128, expert). 8 warps; warp owns 8 row-pairs (4 streams).
// Weights staged gmem->smem via per-warp cp.async, KC=256 floats/stream/stage,
// 8 stages, 3-buffer ring, issue-ahead 2. Each lane copies exactly the
// granules it consumes, so per-thread wait_group is sufficient ordering.
#define GU_ROWS_BLK 128
#define GU_TILES    (INTER / GU_ROWS_BLK)   // 11
#define GU_X_U2     (16*512)                // 8192 u2 = 131072 B
#define GU_WARP_U2  768                     // 3 stages * 4 streams * 64 u2
#define GU_SMEM_B   (131072 + 8*3*4*1024)   // 229376

template<int TM>
__device__ __forceinline__ void gu_rows(const float* __restrict__ wg_e,
                                        const float* __restrict__ wu_e,
                                        const ulonglong2* __restrict__ xs,
                                        const ulonglong2* __restrict__ wsh,
                                        uint32_t wbase,
                                        int row0, int slot0, int rem)
{
    const int warp = threadIdx.x >> 5, lane = threadIdx.x & 31;
    #pragma unroll 1
    for (int rp = 0; rp < 8; rp++) {
        int row = row0 + warp * 16 + rp * 2;
        const float* s0 = wg_e + (size_t)row     * HID;
        const float* s1 = wg_e + (size_t)(row+1) * HID;
        const float* s2 = wu_e + (size_t)row     * HID;
        const float* s3 = wu_e + (size_t)(row+1) * HID;

        ull ag0[TM], ag1[TM], au0[TM], au1[TM];
        #pragma unroll
        for (int t = 0; t < TM; t++) { ag0[t]=0ull; ag1[t]=0ull; au0[t]=0ull; au1[t]=0ull; }

        // prime stages 0,1
        #pragma unroll
        for (int s = 0; s < 2; s++) {
            uint32_t dst = wbase + s * 4096;
            cpa16(dst +          lane*16,      s0 + s*256 + lane*4);
            cpa16(dst +          (lane+32)*16, s0 + s*256 + (lane+32)*4);
            cpa16(dst + 1024 +   lane*16,      s1 + s*256 + lane*4);
            cpa16(dst + 1024 +   (lane+32)*16, s1 + s*256 + (lane+32)*4);
            cpa16(dst + 2048 +   lane*16,      s2 + s*256 + lane*4);
            cpa16(dst + 2048 +   (lane+32)*16, s2 + s*256 + (lane+32)*4);
            cpa16(dst + 3072 +   lane*16,      s3 + s*256 + lane*4);
            cpa16(dst + 3072 +   (lane+32)*16, s3 + s*256 + (lane+32)*4);
            cpa_commit();
        }

        int buf = 0, nbuf = 2;   // buffer of stage s, buffer for stage s+2
        #pragma unroll 1
        for (int s = 0; s < 8; s++) {
            cpa_wait1();                       // stage s arrived
            if (s + 2 < 8) {                   // issue stage s+2
                uint32_t dst = wbase + nbuf * 4096;
                int ko = (s + 2) * 256;
                cpa16(dst +        lane*16,      s0 + ko + lane*4);
                cpa16(dst +        (lane+32)*16, s0 + ko + (lane+32)*4);
                cpa16(dst + 1024 + lane*16,      s1 + ko + lane*4);
                cpa16(dst + 1024 + (lane+32)*16, s1 + ko + (lane+32)*4);
                cpa16(dst + 2048 + lane*16,      s2 + ko + lane*4);
                cpa16(dst + 2048 + (lane+32)*16, s2 + ko + (lane+32)*4);
                cpa16(dst + 3072 + lane*16,      s3 + ko + lane*4);
                cpa16(dst + 3072 + (lane+32)*16, s3 + ko + (lane+32)*4);
            }
            cpa_commit();                      // empty group near the tail keeps count uniform

            const ulonglong2* wb = wsh + buf * 256;
            #pragma unroll
            for (int i = 0; i < 2; i++) {
                int o = lane + (i << 5);
                ulonglong2 a0 = wb[o], a1 = wb[64+o], b0 = wb[128+o], b1 = wb[192+o];
                int xo = s * 64 + o;
                #pragma unroll
                for (int t = 0; t < TM; t++) {
                    ulonglong2 xv = xs[t * 512 + xo];
                    fma2(ag0[t], a0.x, xv.x); fma2(ag0[t], a0.y, xv.y);
                    fma2(ag1[t], a1.x, xv.x); fma2(ag1[t], a1.y, xv.y);
                    fma2(au0[t], b0.x, xv.x); fma2(au0[t], b0.y, xv.y);
                    fma2(au1[t], b1.x, xv.x); fma2(au1[t], b1.y, xv.y);
                }
            }
            buf = buf == 2 ? 0 : buf + 1;
            nbuf = nbuf == 2 ? 0 : nbuf + 1;
        }

        #pragma unroll
        for (int t = 0; t < TM; t++) {
            float gA = hsum(ag0[t]);
            float gB = hsum(ag1[t]);
            float uA = hsum(au0[t]);
            float uB = hsum(au1[t]);
            if (lane == t && t < rem) {
                float sA = gA * __frcp_rn(1.f + __expf(-gA));
                float sB = gB * __frcp_rn(1.f + __expf(-gB));
                float* mp = g_mixed + (size_t)(slot0 + t) * INTER;
                mp[row]     = sA * uA;
                mp[row + 1] = sB * uB;
            }
        }
    }
}

__global__ void __launch_bounds__(256, 1) gateup_k(const float* __restrict__ x,
                                                   const float* __restrict__ wg,
                                                   const float* __restrict__ wu)
{
    extern __shared__ ulonglong2 sh[];
    int e = blockIdx.y;
    int cnt = g_cnt[e];
    if (cnt == 0) return;
    int base = g_off[e];
    int row0 = blockIdx.x * GU_ROWS_BLK;
    const float* wg_e = wg + (size_t)e * INTER * HID;
    const float* wu_e = wu + (size_t)e * INTER * HID;

    uint32_t smem_u32 = (uint32_t)__cvta_generic_to_shared(sh);
    int warp = threadIdx.x >> 5;
    uint32_t wbase = smem_u32 + 131072 + warp * 12288;
    const ulonglong2* wsh = sh + GU_X_U2 + warp * GU_WARP_U2;

    for (int c0 = 0; c0 < cnt; c0 += 16) {
        int rem = cnt - c0; if (rem > 16) rem = 16;
        int tmv = rem <= 8 ? 8 : 16;
        __syncthreads();
        for (int idx = threadIdx.x; idx < tmv * 512; idx += 256) {
            int slot = idx >> 9, j = idx & 511;
            ulonglong2 v;
            if (slot < rem) {
                int tok = g_tok[base + c0 + slot];
                v = reinterpret_cast<const ulonglong2*>(x + (size_t)tok * HID)[j];
            } else { v.x = 0ull; v.y = 0ull; }
            sh[idx] = v;
        }
        __syncthreads();
        if (tmv == 8) gu_rows<8 >(wg_e, wu_e, sh, wsh, wbase, row0, base + c0, rem);
        else          gu_rows<16>(wg_e, wu_e, sh, wsh, wbase, row0, base + c0, rem);
    }
}

// ================= 3) down GEMM: M=cnt, N=2048, K=1408 =================
// warp owns 4 row-quads (4 streams). KC=128 floats/stream/stage, 11 stages.
#define DN_ROWS_BLK 128
#define DN_TILES    (HID / DN_ROWS_BLK)     // 16
#define DN_X_U2     (16*352)                // 5632 u2 = 90112 B
#define DN_WARP_U2  384                     // 3 stages * 4 streams * 32 u2
#define DN_SMEM_B   (90112 + 8*3*4*512)     // 139264

template<int TM>
__device__ __forceinline__ void dn_rows(const float* __restrict__ wd_e,
                                        const ulonglong2* __restrict__ xs,
                                        const ulonglong2* __restrict__ wsh,
                                        uint32_t wbase,
                                        int row0, int slot0, int rem)
{
    const int warp = threadIdx.x >> 5, lane = threadIdx.x & 31;
    #pragma unroll 1
    for (int q = 0; q < 4; q++) {
        int row = row0 + warp * 16 + q * 4;
        const float* s0 = wd_e + (size_t)(row  ) * INTER;
        const float* s1 = wd_e + (size_t)(row+1) * INTER;
        const float* s2 = wd_e + (size_t)(row+2) * INTER;
        const float* s3 = wd_e + (size_t)(row+3) * INTER;

        ull a0[TM], a1[TM], a2[TM], a3[TM];
        #pragma unroll
        for (int t = 0; t < TM; t++) { a0[t]=0ull; a1[t]=0ull; a2[t]=0ull; a3[t]=0ull; }

        #pragma unroll
        for (int s = 0; s < 2; s++) {
            uint32_t dst = wbase + s * 2048;
            cpa16(dst +         lane*16, s0 + s*128 + lane*4);
            cpa16(dst +  512 +  lane*16, s1 + s*128 + lane*4);
            cpa16(dst + 1024 +  lane*16, s2 + s*128 + lane*4);
            cpa16(dst + 1536 +  lane*16, s3 + s*128 + lane*4);
            cpa_commit();
        }

        int buf = 0, nbuf = 2;
        #pragma unroll 1
        for (int s = 0; s < 11; s++) {
            cpa_wait1();
            if (s + 2 < 11) {
                uint32_t dst = wbase + nbuf * 2048;
                int ko = (s + 2) * 128;
                cpa16(dst +         lane*16, s0 + ko + lane*4);
                cpa16(dst +  512 +  lane*16, s1 + ko + lane*4);
                cpa16(dst + 1024 +  lane*16, s2 + ko + lane*4);
                cpa16(dst + 1536 +  lane*16, s3 + ko + lane*4);
            }
            cpa_commit();

            const ulonglong2* wb = wsh + buf * 128;
            ulonglong2 w0 = wb[lane], w1 = wb[32+lane], w2 = wb[64+lane], w3 = wb[96+lane];
            int xo = s * 32 + lane;
            #pragma unroll
            for (int t = 0; t < TM; t++) {
                ulonglong2 xv = xs[t * 352 + xo];
                fma2(a0[t], w0.x, xv.x); fma2(a0[t], w0.y, xv.y);
                fma2(a1[t], w1.x, xv.x); fma2(a1[t], w1.y, xv.y);
                fma2(a2[t], w2.x, xv.x); fma2(a2[t], w2.y, xv.y);
                fma2(a3[t], w3.x, xv.x); fma2(a3[t], w3.y, xv.y);
            }
            buf = buf == 2 ? 0 : buf + 1;
            nbuf = nbuf == 2 ? 0 : nbuf + 1;
        }

        #pragma unroll
        for (int t = 0; t < TM; t++) {
            float v0 = hsum(a0[t]);
            float v1 = hsum(a1[t]);
            float v2 = hsum(a2[t]);
            float v3 = hsum(a3[t]);
            if (lane == t && t < rem) {
                float w = g_wass[slot0 + t];
                float* pp = g_part + (size_t)(slot0 + t) * HID;
                pp[row]     = v0 * w;
                pp[row + 1] = v1 * w;
                pp[row + 2] = v2 * w;
                pp[row + 3] = v3 * w;
            }
        }
    }
}

__global__ void __launch_bounds__(256, 1) down_k(const float* __restrict__ wd)
{
    extern __shared__ ulonglong2 sh[];
    int e = blockIdx.y;
    int cnt = g_cnt[e];
    if (cnt == 0) return;
    int base = g_off[e];
    int row0 = blockIdx.x * DN_ROWS_BLK;
    const float* wd_e = wd + (size_t)e * HID * INTER;

    uint32_t smem_u32 = (uint32_t)__cvta_generic_to_shared(sh);
    int warp = threadIdx.x >> 5;
    uint32_t wbase = smem_u32 + 90112 + warp * 6144;
    const ulonglong2* wsh = sh + DN_X_U2 + warp * DN_WARP_U2;

    for (int c0 = 0; c0 < cnt; c0 += 16) {
        int rem = cnt - c0; if (rem > 16) rem = 16;
        int tmv = rem <= 8 ? 8 : 16;
        __syncthreads();
        for (int idx = threadIdx.x; idx < tmv * 352; idx += 256) {
            int slot = idx / 352, j = idx - slot * 352;
            ulonglong2 v;
            if (slot < rem) {
                v = reinterpret_cast<const ulonglong2*>(g_mixed + (size_t)(base + c0 + slot) * INTER)[j];
            } else { v.x = 0ull; v.y = 0ull; }
            sh[idx] = v;
        }
        __syncthreads();
        if (tmv == 8) dn_rows<8 >(wd_e, sh, wsh, wbase, row0, base + c0, rem);
        else          dn_rows<16>(wd_e, sh, wsh, wbase, row0, base + c0, rem);
    }
}

// ---------------- 4) gather ----------------
__global__ void gather_k(float* __restrict__ out)
{
    int idx = blockIdx.x * 256 + threadIdx.x;
    int t = idx >> 11;
    int h = idx & 2047;
    const int* ai = g_aidx + t * TOPK;
    float s = 0.f;
    #pragma unroll
    for (int j = 0; j < TOPK; j++) s += g_part[(size_t)ai[j] * HID + h];
    out[idx] = s;
}

// ---------------- launch ----------------
extern "C" void kernel_launch(void* const* d_in, const int* in_sizes, int n_in,
                              void* d_out, int out_size)
{
    const float* x      = (const float*)d_in[0];
    const float* logits = (const float*)d_in[1];
    const float* wg     = (const float*)d_in[2];
    const float* wu     = (const float*)d_in[3];
    const float* wd     = (const float*)d_in[4];
    float* out = (float*)d_out;

    cudaFuncSetAttribute(gateup_k, cudaFuncAttributeMaxDynamicSharedMemorySize, GU_SMEM_B);
    cudaFuncSetAttribute(down_k,   cudaFuncAttributeMaxDynamicSharedMemorySize, DN_SMEM_B);

    route_k<<<1, NTOK>>>(logits);
    gateup_k<<<dim3(GU_TILES, NEXP), 256, GU_SMEM_B>>>(x, wg, wu);
    down_k  <<<dim3(DN_TILES, NEXP), 256, DN_SMEM_B>>>(wd);
    gather_k<<<(NTOK * HID) / 256, 256>>>(out);
}